// round 12
// baseline (speedup 1.0000x reference)
#include <cuda_runtime.h>
#include <cstdint>

#define N_DOC   20000
#define N_WORD  80000
#define N_NODES 100000
#define HID     64
#define M_MASK  10000
#define E_EDGES 1000000

// ---------------- scratch (static __device__, allocation-free) ----------------
__device__ __align__(256) float g_xw1 [N_NODES * HID];  // x @ W1 (pre-aggregation)
__device__ __align__(256) float g_agg1[N_NODES * HID];  // layer1 neighbor sum
__device__ __align__(256) float g_h1  [N_NODES * HID];  // relu(layer1)
__device__ __align__(256) float g_xw2 [N_NODES * HID];  // h1 @ W2
__device__ __align__(256) float g_agg2[N_NODES * HID];  // layer2 neighbor sum
__device__ __align__(256) float g_deg [N_NODES];
__device__ __align__(256) float g_dis [N_NODES];
__device__ __align__(256) float g_Weff[300 * HID];      // W_lin @ W1
__device__ __align__(256) float g_bword[HID];           // b_lin @ W1
__device__ unsigned char g_maskflag[N_NODES];
__device__ int g_mcount;                                 // # masked-dst edges
__device__ int g_medges[E_EDGES];                        // compacted edge ids

// ---------------- init: zero accumulators, deg=1 (self loop), flags=0 ---------
__global__ void init_kernel() {
    int idx = blockIdx.x * blockDim.x + threadIdx.x;
    if (idx < N_NODES * HID) {
        g_agg1[idx] = 0.f;
        g_agg2[idx] = 0.f;
    }
    if (idx < N_NODES) {
        g_deg[idx] = 1.0f;      // self-loop weight
        g_maskflag[idx] = 0;
    }
    if (idx == 0) g_mcount = 0;
}

__global__ void mask_set_kernel(const int* __restrict__ mask_idx) {
    int idx = blockIdx.x * blockDim.x + threadIdx.x;
    if (idx < M_MASK) {
        unsigned n = (unsigned)mask_idx[idx];
        if (n < N_NODES) g_maskflag[n] = 1;
    }
}

// ---------------- degree accumulation + masked-edge compaction ----------------
__global__ void deg_compact_kernel(const int* __restrict__ cols,
                                   const float* __restrict__ w, int E) {
    __shared__ int s_cnt, s_base;
    if (threadIdx.x == 0) s_cnt = 0;
    __syncthreads();
    int idx = blockIdx.x * blockDim.x + threadIdx.x;
    int slot = -1;
    if (idx < E) {
        unsigned c = (unsigned)cols[idx];
        if (c < N_NODES) {
            atomicAdd(&g_deg[c], w[idx]);
            if (g_maskflag[c]) slot = atomicAdd(&s_cnt, 1);
        }
    }
    __syncthreads();
    if (threadIdx.x == 0) s_base = atomicAdd(&g_mcount, s_cnt);
    __syncthreads();
    if (slot >= 0) g_medges[s_base + slot] = idx;
}

__global__ void dis_kernel() {
    int idx = blockIdx.x * blockDim.x + threadIdx.x;
    if (idx < N_NODES) g_dis[idx] = rsqrtf(g_deg[idx]);   // deg >= 1 always
}

// ---------------- W_eff = W_lin @ W1 ; b_word = b_lin @ W1 --------------------
__global__ void weff_kernel(const float* __restrict__ W_lin,
                            const float* __restrict__ W1,
                            const float* __restrict__ b_lin) {
    int tid = blockIdx.x * blockDim.x + threadIdx.x;
    if (tid < 300 * HID) {
        int n = tid & 63, r = tid >> 6;
        float s = 0.f;
        #pragma unroll 8
        for (int k = 0; k < 768; k++) s += W_lin[r * 768 + k] * W1[k * 64 + n];
        g_Weff[tid] = s;
    } else if (tid < 301 * HID) {
        int n = tid & 63;
        float s = 0.f;
        #pragma unroll 8
        for (int k = 0; k < 768; k++) s += b_lin[k] * W1[k * 64 + n];
        g_bword[n] = s;
    }
}

// ---------------- helpers: tf32 split -----------------------------------------
__device__ __forceinline__ unsigned tf32_of(float v) {
    unsigned u;
    asm("cvt.rna.tf32.f32 %0, %1;" : "=r"(u) : "f"(v));
    return u;
}

#define MMA_TF32(d, a, b)                                                     \
    asm volatile("mma.sync.aligned.m16n8k8.row.col.f32.tf32.tf32.f32 "        \
                 "{%0,%1,%2,%3}, {%4,%5,%6,%7}, {%8,%9}, {%0,%1,%2,%3};"      \
                 : "+f"((d)[0]), "+f"((d)[1]), "+f"((d)[2]), "+f"((d)[3])     \
                 : "r"((a)[0]), "r"((a)[1]), "r"((a)[2]), "r"((a)[3]),        \
                   "r"((b)[0]), "r"((b)[1]))

// ---------------- GEMM: C[M,64] = A[M,K] @ B[K,64] (+bias), split-TF32 MMA ----
// BM=128, BN=64, BK=16, 256 threads = 8 warps in a 4(m) x 2(n) grid;
// each warp computes 32x32 via m16n8k8 tf32 mma. Full-precision via split:
// a = a_hi + a_lo (tf32 each), b likewise; D += ah*bh + ah*bl + al*bh
// (lo*lo term ~2^-22 relative, dropped). rel_err stays ~fp32-level.
// Smem layouts conflict-free for fragment access patterns:
//   As[128][36]: row stride 36 (== 4 mod 32) -> addr = m*4 + k distinct banks
//   Bs[16][72] : row stride 72 (== 8 mod 32) -> addr = k*8 + n distinct banks
__global__ __launch_bounds__(256)
void gemm64_kernel(const float* __restrict__ Ap,
                   const float* __restrict__ Bp,
                   int a_sel, int b_sel, int bias_sel, int c_sel,
                   long long c_off, int M, int K) {
    const int BM = 128, BK = 16;
    __shared__ float As_hi[BM][36];
    __shared__ float As_lo[BM][36];
    __shared__ float Bs_hi[BK][72];
    __shared__ float Bs_lo[BK][72];
    const float* A = a_sel ? g_h1 : Ap;
    const float* B = b_sel ? g_Weff : Bp;
    float* C = (c_sel ? g_xw2 : g_xw1) + c_off;

    int tid  = threadIdx.x;
    int bm   = blockIdx.x * BM;
    int lane = tid & 31;
    int wid  = tid >> 5;        // 0..7
    int wm   = wid & 3;         // warp row block: rows wm*32
    int wn   = wid >> 2;        // warp col block: cols wn*32
    int g    = lane >> 2;       // 0..7
    int t    = lane & 3;        // 0..3

    // global-load mappings (as R10)
    int am  = tid >> 1;         // 0..127
    int akq = (tid & 1) * 8;    // 0 or 8
    int bk  = tid >> 4;         // 0..15
    int bn  = (tid & 15) * 4;   // 0..60

    float acc[2][4][4];
    #pragma unroll
    for (int mi = 0; mi < 2; mi++)
        #pragma unroll
        for (int ni = 0; ni < 4; ni++)
            #pragma unroll
            for (int r = 0; r < 4; r++) acc[mi][ni][r] = 0.f;

    for (int k0 = 0; k0 < K; k0 += BK) {
        // ---- A tile: rows bm..bm+127, cols k0..k0+15 ----
        {
            int gm = bm + am;
            float v[8];
            if (gm < M && k0 + BK <= K) {
                const float* src = A + (size_t)gm * K + k0 + akq;
                float4 v0 = *(const float4*)src;
                float4 v1 = *(const float4*)(src + 4);
                v[0] = v0.x; v[1] = v0.y; v[2] = v0.z; v[3] = v0.w;
                v[4] = v1.x; v[5] = v1.y; v[6] = v1.z; v[7] = v1.w;
            } else {
                #pragma unroll
                for (int j = 0; j < 8; j++) {
                    int gk = k0 + akq + j;
                    v[j] = (gm < M && gk < K) ? A[(size_t)gm * K + gk] : 0.f;
                }
            }
            #pragma unroll
            for (int j = 0; j < 8; j++) {
                float hif = __uint_as_float(tf32_of(v[j]));
                float lof = v[j] - hif;
                As_hi[am][akq + j] = hif;
                As_lo[am][akq + j] = __uint_as_float(tf32_of(lof));
            }
        }
        // ---- B tile: rows k0..k0+15, 64 cols ----
        {
            int gk = k0 + bk;
            float4 bv = make_float4(0.f, 0.f, 0.f, 0.f);
            if (gk < K) bv = *(const float4*)&B[gk * 64 + bn];
            float bb[4] = {bv.x, bv.y, bv.z, bv.w};
            #pragma unroll
            for (int j = 0; j < 4; j++) {
                float hif = __uint_as_float(tf32_of(bb[j]));
                float lof = bb[j] - hif;
                Bs_hi[bk][bn + j] = hif;
                Bs_lo[bk][bn + j] = __uint_as_float(tf32_of(lof));
            }
        }
        __syncthreads();
        #pragma unroll
        for (int kk = 0; kk < BK; kk += 8) {
            unsigned ah[2][4], al[2][4];
            #pragma unroll
            for (int mi = 0; mi < 2; mi++) {
                int mr = wm * 32 + mi * 16 + g;
                ah[mi][0] = __float_as_uint(As_hi[mr    ][kk + t]);
                ah[mi][1] = __float_as_uint(As_hi[mr + 8][kk + t]);
                ah[mi][2] = __float_as_uint(As_hi[mr    ][kk + t + 4]);
                ah[mi][3] = __float_as_uint(As_hi[mr + 8][kk + t + 4]);
                al[mi][0] = __float_as_uint(As_lo[mr    ][kk + t]);
                al[mi][1] = __float_as_uint(As_lo[mr + 8][kk + t]);
                al[mi][2] = __float_as_uint(As_lo[mr    ][kk + t + 4]);
                al[mi][3] = __float_as_uint(As_lo[mr + 8][kk + t + 4]);
            }
            unsigned bh[4][2], bl[4][2];
            #pragma unroll
            for (int ni = 0; ni < 4; ni++) {
                int nc = wn * 32 + ni * 8 + g;
                bh[ni][0] = __float_as_uint(Bs_hi[kk + t    ][nc]);
                bh[ni][1] = __float_as_uint(Bs_hi[kk + t + 4][nc]);
                bl[ni][0] = __float_as_uint(Bs_lo[kk + t    ][nc]);
                bl[ni][1] = __float_as_uint(Bs_lo[kk + t + 4][nc]);
            }
            #pragma unroll
            for (int mi = 0; mi < 2; mi++)
                #pragma unroll
                for (int ni = 0; ni < 4; ni++) {
                    MMA_TF32(acc[mi][ni], ah[mi], bh[ni]);
                    MMA_TF32(acc[mi][ni], ah[mi], bl[ni]);
                    MMA_TF32(acc[mi][ni], al[mi], bh[ni]);
                }
        }
        __syncthreads();
    }
    // ---- epilogue: C fragment layout c0,c1 @ (g, 2t..2t+1), c2,c3 @ (g+8, ..)
    #pragma unroll
    for (int mi = 0; mi < 2; mi++) {
        int r0 = bm + wm * 32 + mi * 16 + g;
        #pragma unroll
        for (int ni = 0; ni < 4; ni++) {
            int c = wn * 32 + ni * 8 + 2 * t;
            float2 p0, p1;
            p0.x = acc[mi][ni][0]; p0.y = acc[mi][ni][1];
            p1.x = acc[mi][ni][2]; p1.y = acc[mi][ni][3];
            if (bias_sel) {
                float bx = g_bword[c], by = g_bword[c + 1];
                p0.x += bx; p0.y += by; p1.x += bx; p1.y += by;
            }
            if (r0 < M)     *(float2*)&C[(size_t)r0 * 64 + c] = p0;
            if (r0 + 8 < M) *(float2*)&C[(size_t)(r0 + 8) * 64 + c] = p1;
        }
    }
}

// ---------------- layer-1 scatter: agg1[col] += coef * xw1[row] ---------------
// Half-warp per edge; lane sub handles features 4*sub..4*sub+3 via float4
// gather + one red.global.add.v4.f32 (16 vector REDs per edge).
__global__ void scatter1_kernel(const int* __restrict__ rows,
                                const int* __restrict__ cols,
                                const float* __restrict__ w, int E) {
    int hw  = (blockIdx.x * blockDim.x + threadIdx.x) >> 4;   // edge id
    int sub = threadIdx.x & 15;
    if (hw >= E) return;
    unsigned c = (unsigned)cols[hw];
    if (c >= N_NODES) return;
    unsigned r = (unsigned)rows[hw];
    if (r >= N_NODES) return;
    float coef = g_dis[r] * w[hw] * g_dis[c];
    float4 v = *(const float4*)(g_xw1 + (size_t)r * 64 + sub * 4);
    v.x *= coef; v.y *= coef; v.z *= coef; v.w *= coef;
    float* dst = g_agg1 + (size_t)c * 64 + sub * 4;
    asm volatile("red.global.add.v4.f32 [%0], {%1, %2, %3, %4};"
                 :: "l"(dst), "f"(v.x), "f"(v.y), "f"(v.z), "f"(v.w) : "memory");
}

// ---------------- layer-2 scatter over compacted masked-dst edges -------------
__global__ void scatter2_kernel(const int* __restrict__ rows,
                                const int* __restrict__ cols,
                                const float* __restrict__ w) {
    int nhw = (gridDim.x * blockDim.x) >> 4;
    int hw0 = (blockIdx.x * blockDim.x + threadIdx.x) >> 4;
    int sub = threadIdx.x & 15;
    int cnt = g_mcount;
    for (int i = hw0; i < cnt; i += nhw) {
        int e = g_medges[i];
        unsigned c = (unsigned)cols[e];
        unsigned r = (unsigned)rows[e];
        if (c >= N_NODES || r >= N_NODES) continue;
        float coef = g_dis[r] * w[e] * g_dis[c];
        float4 v = *(const float4*)(g_xw2 + (size_t)r * 64 + sub * 4);
        v.x *= coef; v.y *= coef; v.z *= coef; v.w *= coef;
        float* dst = g_agg2 + (size_t)c * 64 + sub * 4;
        asm volatile("red.global.add.v4.f32 [%0], {%1, %2, %3, %4};"
                     :: "l"(dst), "f"(v.x), "f"(v.y), "f"(v.z), "f"(v.w) : "memory");
    }
}

// ---------------- h1 = relu(agg1 + dis^2 * xw1 + b1)  (self-loop folded) ------
__global__ void relu_combine_kernel(const float* __restrict__ b1) {
    int idx = blockIdx.x * blockDim.x + threadIdx.x;
    if (idx < N_NODES * HID) {
        int i = idx >> 6, j = idx & 63;
        float d = g_dis[i];
        float v = g_agg1[idx] + d * d * g_xw1[idx] + b1[j];
        g_h1[idx] = v > 0.f ? v : 0.f;
    }
}

// ---------------- final: out = agg2[node] + dis^2*xw2[node] + b2, gather y ----
__global__ void final_kernel(const int* __restrict__ mask_idx,
                             const int* __restrict__ y,
                             const float* __restrict__ b2,
                             float* __restrict__ out, int write_y) {
    int idx = blockIdx.x * blockDim.x + threadIdx.x;
    if (idx < M_MASK * HID) {
        int i = idx >> 6, j = idx & 63;
        unsigned node = (unsigned)mask_idx[i];
        if (node < N_NODES) {
            float d = g_dis[node];
            out[idx] = g_agg2[(size_t)node * 64 + j]
                     + d * d * g_xw2[(size_t)node * 64 + j] + b2[j];
        } else {
            out[idx] = 0.f;
        }
    }
    if (write_y && idx < M_MASK) {
        unsigned node = (unsigned)mask_idx[idx];
        out[M_MASK * HID + idx] = (node < N_NODES) ? (float)y[node] : 0.f;
    }
}

// ---------------- launch ------------------------------------------------------
extern "C" void kernel_launch(void* const* d_in, const int* in_sizes, int n_in,
                              void* d_out, int out_size) {
    const float *doc = nullptr, *word = nullptr, *ew = nullptr;
    const float *W_lin = nullptr, *b_lin = nullptr, *W1 = nullptr, *b1 = nullptr;
    const float *b2 = nullptr, *W2 = nullptr;
    const int *edge_index = nullptr, *mask_idx = nullptr, *yv = nullptr;  // int32
    for (int i = 0; i < n_in; i++) {
        switch (in_sizes[i]) {
            case N_DOC * 768:       doc       = (const float*)d_in[i]; break;
            case N_WORD * 300:      word      = (const float*)d_in[i]; break;
            case E_EDGES:           ew        = (const float*)d_in[i]; break;
            case 300 * 768:         W_lin     = (const float*)d_in[i]; break;
            case 768:               b_lin     = (const float*)d_in[i]; break;
            case 768 * HID:         W1        = (const float*)d_in[i]; break;
            case HID * HID:         W2        = (const float*)d_in[i]; break;
            case 2 * E_EDGES:       edge_index= (const int*)d_in[i]; break;
            case M_MASK:            mask_idx  = (const int*)d_in[i]; break;
            case N_NODES:           yv        = (const int*)d_in[i]; break;
            case HID:               if (!b1) b1 = (const float*)d_in[i];   // W1,b1 precede W2,b2
                                    else     b2 = (const float*)d_in[i]; break;
            default: break;
        }
    }
    const int E = E_EDGES;
    const int* rows = edge_index;       // edge_index[0]
    const int* cols = edge_index + E;   // edge_index[1]

    float* out = (float*)d_out;
    int write_y = (out_size >= M_MASK * HID + M_MASK) ? 1 : 0;

    const int T = 256;
    // 1) init accumulators / deg / flags / counter
    init_kernel<<<(N_NODES * HID + T - 1) / T, T>>>();
    // 2) mask flags (must precede deg_compact)
    mask_set_kernel<<<(M_MASK + T - 1) / T, T>>>(mask_idx);
    // 3) fused weight W_eff = W_lin@W1, b_word = b_lin@W1
    weff_kernel<<<(301 * HID + T - 1) / T, T>>>(W_lin, W1, b_lin);
    // 4) degree + masked-edge compaction + normalization
    deg_compact_kernel<<<(E + T - 1) / T, T>>>(cols, ew, E);
    dis_kernel<<<(N_NODES + T - 1) / T, T>>>();
    // 5) xw1: doc part = doc@W1 ; word part = word@W_eff + b_word
    gemm64_kernel<<<(N_DOC + 127) / 128, 256>>>(doc, W1, 0, 0, 0, 0,
                                                0, N_DOC, 768);
    gemm64_kernel<<<(N_WORD + 127) / 128, 256>>>(word, nullptr, 0, 1, 1, 0,
                                                 (long long)N_DOC * HID, N_WORD, 300);
    // 6) layer-1 aggregation: half-warp per edge, vector REDs
    {
        int edges_per_block = T / 16;  // 16
        scatter1_kernel<<<(E + edges_per_block - 1) / edges_per_block, T>>>(
            rows, cols, ew, E);
    }
    relu_combine_kernel<<<(N_NODES * HID + T - 1) / T, T>>>(b1);
    // 7) layer 2
    gemm64_kernel<<<(N_NODES + 127) / 128, 256>>>(nullptr, W2, 1, 0, 0, 1,
                                                  0, N_NODES, 64);
    scatter2_kernel<<<1024, T>>>(rows, cols, ew);
    // 8) output gather
    final_kernel<<<(M_MASK * HID + T - 1) / T, T>>>(mask_idx, yv, b2, out, write_y);
}

// round 14
// speedup vs baseline: 1.1453x; 1.1453x over previous
#include <cuda_runtime.h>
#include <cstdint>

#define N_DOC   20000
#define N_WORD  80000
#define N_NODES 100000
#define HID     64
#define M_MASK  10000
#define E_EDGES 1000000

// ---------------- scratch (static __device__, allocation-free) ----------------
__device__ __align__(256) float g_xw1 [N_NODES * HID];  // x @ W1 (pre-aggregation)
__device__ __align__(256) float g_agg1[N_NODES * HID];  // layer1 neighbor sum
__device__ __align__(256) float g_xw2 [N_NODES * HID];  // h1 @ W2
__device__ __align__(256) float g_agg2[N_NODES * HID];  // layer2 neighbor sum
__device__ __align__(256) float g_deg [N_NODES];
__device__ __align__(256) float g_dis [N_NODES];
__device__ __align__(256) float g_Weff[300 * HID];      // W_lin @ W1
__device__ __align__(256) float g_bword[HID];           // b_lin @ W1
__device__ unsigned char g_maskflag[N_NODES];
__device__ int g_mcount;                                 // # masked-dst edges
__device__ int g_medges[E_EDGES];                        // compacted edge ids

// ---------------- init: zero accumulators, deg=1 (self loop), flags=0 ---------
__global__ void init_kernel() {
    int idx = blockIdx.x * blockDim.x + threadIdx.x;
    if (idx < N_NODES * HID) {
        g_agg1[idx] = 0.f;
        g_agg2[idx] = 0.f;
    }
    if (idx < N_NODES) {
        g_deg[idx] = 1.0f;      // self-loop weight
        g_maskflag[idx] = 0;
    }
    if (idx == 0) g_mcount = 0;
}

__global__ void mask_set_kernel(const int* __restrict__ mask_idx) {
    int idx = blockIdx.x * blockDim.x + threadIdx.x;
    if (idx < M_MASK) {
        unsigned n = (unsigned)mask_idx[idx];
        if (n < N_NODES) g_maskflag[n] = 1;
    }
}

// ---------------- degree accumulation + masked-edge compaction ----------------
__global__ void deg_compact_kernel(const int* __restrict__ cols,
                                   const float* __restrict__ w, int E) {
    __shared__ int s_cnt, s_base;
    if (threadIdx.x == 0) s_cnt = 0;
    __syncthreads();
    int idx = blockIdx.x * blockDim.x + threadIdx.x;
    int slot = -1;
    if (idx < E) {
        unsigned c = (unsigned)cols[idx];
        if (c < N_NODES) {
            atomicAdd(&g_deg[c], w[idx]);
            if (g_maskflag[c]) slot = atomicAdd(&s_cnt, 1);
        }
    }
    __syncthreads();
    if (threadIdx.x == 0) s_base = atomicAdd(&g_mcount, s_cnt);
    __syncthreads();
    if (slot >= 0) g_medges[s_base + slot] = idx;
}

__global__ void dis_kernel() {
    int idx = blockIdx.x * blockDim.x + threadIdx.x;
    if (idx < N_NODES) g_dis[idx] = rsqrtf(g_deg[idx]);   // deg >= 1 always
}

// ---------------- W_eff = W_lin @ W1 ; b_word = b_lin @ W1 --------------------
__global__ void weff_kernel(const float* __restrict__ W_lin,
                            const float* __restrict__ W1,
                            const float* __restrict__ b_lin) {
    int tid = blockIdx.x * blockDim.x + threadIdx.x;
    if (tid < 300 * HID) {
        int n = tid & 63, r = tid >> 6;
        float s = 0.f;
        #pragma unroll 8
        for (int k = 0; k < 768; k++) s += W_lin[r * 768 + k] * W1[k * 64 + n];
        g_Weff[tid] = s;
    } else if (tid < 301 * HID) {
        int n = tid & 63;
        float s = 0.f;
        #pragma unroll 8
        for (int k = 0; k < 768; k++) s += b_lin[k] * W1[k * 64 + n];
        g_bword[n] = s;
    }
}

// ---------------- GEMM: C[M,64] = A[M,K] @ B[K,64] (+bias) --------------------
// BM=128, BN=64, BK=16, 256 threads, 8x4 per thread, plain FFMA.
// Software-pipelined: double-buffered smem, tile t+1 prefetched into registers
// during compute of tile t, ONE __syncthreads per k-tile.
// a_sel==1: A = relu(g_agg1 + dis^2 * g_xw1 + bias1) computed on the fly
// (fused layer-1 epilogue; requires K == HID).
__global__ __launch_bounds__(256)
void gemm64_kernel(const float* __restrict__ Ap,
                   const float* __restrict__ Bp,
                   const float* __restrict__ bias1,
                   int a_sel, int b_sel, int bias_sel, int c_sel,
                   long long c_off, int M, int K) {
    const int BM = 128, BK = 16;
    __shared__ float As[2][BK][BM + 4];
    __shared__ float Bs[2][BK][64];
    const float* A = Ap;
    const float* B = b_sel ? g_Weff : Bp;
    float* C = (c_sel ? g_xw2 : g_xw1) + c_off;

    int tid  = threadIdx.x;
    int bm   = blockIdx.x * BM;
    int trow = tid >> 4;        // 0..15
    int tcol = tid & 15;        // 0..15

    // load mappings
    int am  = tid >> 1;         // 0..127
    int akq = (tid & 1) * 8;    // 0 or 8
    int bk  = tid >> 4;         // 0..15
    int bn  = (tid & 15) * 4;   // 0..60

    float acc[8][4];
    #pragma unroll
    for (int i = 0; i < 8; i++)
        #pragma unroll
        for (int j = 0; j < 4; j++) acc[i][j] = 0.f;

    int ntiles = (K + BK - 1) / BK;
    float ra[8];
    float rb[4];

    // ---- tile loader into registers ----
    auto load_tile = [&](int t) {
        int k0 = t * BK;
        int gm = bm + am;
        if (a_sel == 0) {
            if (gm < M && k0 + BK <= K) {
                const float* src = A + (size_t)gm * K + k0 + akq;
                float4 v0 = *(const float4*)src;
                float4 v1 = *(const float4*)(src + 4);
                ra[0] = v0.x; ra[1] = v0.y; ra[2] = v0.z; ra[3] = v0.w;
                ra[4] = v1.x; ra[5] = v1.y; ra[6] = v1.z; ra[7] = v1.w;
            } else {
                #pragma unroll
                for (int j = 0; j < 8; j++) {
                    int gk = k0 + akq + j;
                    ra[j] = (gm < M && gk < K) ? A[(size_t)gm * K + gk] : 0.f;
                }
            }
        } else {
            // fused: A = relu(agg1 + d^2 * xw1 + b1), K == 64 (all tiles full)
            if (gm < M) {
                float d = g_dis[gm];
                float d2 = d * d;
                const float* p = g_agg1 + (size_t)gm * HID + k0 + akq;
                const float* q = g_xw1  + (size_t)gm * HID + k0 + akq;
                float4 p0 = *(const float4*)p;
                float4 p1 = *(const float4*)(p + 4);
                float4 q0 = *(const float4*)q;
                float4 q1 = *(const float4*)(q + 4);
                float pv[8] = {p0.x, p0.y, p0.z, p0.w, p1.x, p1.y, p1.z, p1.w};
                float qv[8] = {q0.x, q0.y, q0.z, q0.w, q1.x, q1.y, q1.z, q1.w};
                #pragma unroll
                for (int j = 0; j < 8; j++) {
                    float v = pv[j] + d2 * qv[j] + bias1[k0 + akq + j];
                    ra[j] = v > 0.f ? v : 0.f;
                }
            } else {
                #pragma unroll
                for (int j = 0; j < 8; j++) ra[j] = 0.f;
            }
        }
        {
            int gk = t * BK + bk;
            float4 bv = make_float4(0.f, 0.f, 0.f, 0.f);
            if (gk < K) bv = *(const float4*)&B[gk * 64 + bn];
            rb[0] = bv.x; rb[1] = bv.y; rb[2] = bv.z; rb[3] = bv.w;
        }
    };
    auto store_tile = [&](int buf) {
        #pragma unroll
        for (int j = 0; j < 8; j++) As[buf][akq + j][am] = ra[j];
        *(float4*)&Bs[buf][bk][bn] = make_float4(rb[0], rb[1], rb[2], rb[3]);
    };

    // prologue
    load_tile(0);
    store_tile(0);
    __syncthreads();

    int cur = 0;
    for (int t = 0; t < ntiles; t++) {
        if (t + 1 < ntiles) load_tile(t + 1);   // prefetch overlaps compute
        #pragma unroll
        for (int k = 0; k < BK; k++) {
            float4 a0 = *(const float4*)&As[cur][k][trow * 8];
            float4 a1 = *(const float4*)&As[cur][k][trow * 8 + 4];
            float4 bv = *(const float4*)&Bs[cur][k][tcol * 4];
            float a[8] = {a0.x, a0.y, a0.z, a0.w, a1.x, a1.y, a1.z, a1.w};
            float b[4] = {bv.x, bv.y, bv.z, bv.w};
            #pragma unroll
            for (int i = 0; i < 8; i++)
                #pragma unroll
                for (int j = 0; j < 4; j++) acc[i][j] += a[i] * b[j];
        }
        if (t + 1 < ntiles) store_tile(cur ^ 1);
        __syncthreads();
        cur ^= 1;
    }

    #pragma unroll
    for (int i = 0; i < 8; i++) {
        int gm = bm + trow * 8 + i;
        if (gm < M) {
            int n = tcol * 4;
            float4 r;
            r.x = acc[i][0]; r.y = acc[i][1]; r.z = acc[i][2]; r.w = acc[i][3];
            if (bias_sel) {
                r.x += g_bword[n]; r.y += g_bword[n + 1];
                r.z += g_bword[n + 2]; r.w += g_bword[n + 3];
            }
            *(float4*)&C[(size_t)gm * 64 + n] = r;
        }
    }
}

// ---------------- layer-1 scatter: agg1[col] += coef * xw1[row] ---------------
// Half-warp per edge; lane sub handles features 4*sub..4*sub+3 via float4
// gather + one red.global.add.v4.f32 (16 vector REDs per edge).
__global__ void scatter1_kernel(const int* __restrict__ rows,
                                const int* __restrict__ cols,
                                const float* __restrict__ w, int E) {
    int hw  = (blockIdx.x * blockDim.x + threadIdx.x) >> 4;   // edge id
    int sub = threadIdx.x & 15;
    if (hw >= E) return;
    unsigned c = (unsigned)cols[hw];
    if (c >= N_NODES) return;
    unsigned r = (unsigned)rows[hw];
    if (r >= N_NODES) return;
    float coef = g_dis[r] * w[hw] * g_dis[c];
    float4 v = *(const float4*)(g_xw1 + (size_t)r * 64 + sub * 4);
    v.x *= coef; v.y *= coef; v.z *= coef; v.w *= coef;
    float* dst = g_agg1 + (size_t)c * 64 + sub * 4;
    asm volatile("red.global.add.v4.f32 [%0], {%1, %2, %3, %4};"
                 :: "l"(dst), "f"(v.x), "f"(v.y), "f"(v.z), "f"(v.w) : "memory");
}

// ---------------- layer-2 scatter over compacted masked-dst edges -------------
__global__ void scatter2_kernel(const int* __restrict__ rows,
                                const int* __restrict__ cols,
                                const float* __restrict__ w) {
    int nhw = (gridDim.x * blockDim.x) >> 4;
    int hw0 = (blockIdx.x * blockDim.x + threadIdx.x) >> 4;
    int sub = threadIdx.x & 15;
    int cnt = g_mcount;
    for (int i = hw0; i < cnt; i += nhw) {
        int e = g_medges[i];
        unsigned c = (unsigned)cols[e];
        unsigned r = (unsigned)rows[e];
        if (c >= N_NODES || r >= N_NODES) continue;
        float coef = g_dis[r] * w[e] * g_dis[c];
        float4 v = *(const float4*)(g_xw2 + (size_t)r * 64 + sub * 4);
        v.x *= coef; v.y *= coef; v.z *= coef; v.w *= coef;
        float* dst = g_agg2 + (size_t)c * 64 + sub * 4;
        asm volatile("red.global.add.v4.f32 [%0], {%1, %2, %3, %4};"
                     :: "l"(dst), "f"(v.x), "f"(v.y), "f"(v.z), "f"(v.w) : "memory");
    }
}

// ---------------- final: out = agg2[node] + dis^2*xw2[node] + b2, gather y ----
__global__ void final_kernel(const int* __restrict__ mask_idx,
                             const int* __restrict__ y,
                             const float* __restrict__ b2,
                             float* __restrict__ out, int write_y) {
    int idx = blockIdx.x * blockDim.x + threadIdx.x;
    if (idx < M_MASK * HID) {
        int i = idx >> 6, j = idx & 63;
        unsigned node = (unsigned)mask_idx[i];
        if (node < N_NODES) {
            float d = g_dis[node];
            out[idx] = g_agg2[(size_t)node * 64 + j]
                     + d * d * g_xw2[(size_t)node * 64 + j] + b2[j];
        } else {
            out[idx] = 0.f;
        }
    }
    if (write_y && idx < M_MASK) {
        unsigned node = (unsigned)mask_idx[idx];
        out[M_MASK * HID + idx] = (node < N_NODES) ? (float)y[node] : 0.f;
    }
}

// ---------------- launch ------------------------------------------------------
extern "C" void kernel_launch(void* const* d_in, const int* in_sizes, int n_in,
                              void* d_out, int out_size) {
    const float *doc = nullptr, *word = nullptr, *ew = nullptr;
    const float *W_lin = nullptr, *b_lin = nullptr, *W1 = nullptr, *b1 = nullptr;
    const float *b2 = nullptr, *W2 = nullptr;
    const int *edge_index = nullptr, *mask_idx = nullptr, *yv = nullptr;  // int32
    for (int i = 0; i < n_in; i++) {
        switch (in_sizes[i]) {
            case N_DOC * 768:       doc       = (const float*)d_in[i]; break;
            case N_WORD * 300:      word      = (const float*)d_in[i]; break;
            case E_EDGES:           ew        = (const float*)d_in[i]; break;
            case 300 * 768:         W_lin     = (const float*)d_in[i]; break;
            case 768:               b_lin     = (const float*)d_in[i]; break;
            case 768 * HID:         W1        = (const float*)d_in[i]; break;
            case HID * HID:         W2        = (const float*)d_in[i]; break;
            case 2 * E_EDGES:       edge_index= (const int*)d_in[i]; break;
            case M_MASK:            mask_idx  = (const int*)d_in[i]; break;
            case N_NODES:           yv        = (const int*)d_in[i]; break;
            case HID:               if (!b1) b1 = (const float*)d_in[i];   // W1,b1 precede W2,b2
                                    else     b2 = (const float*)d_in[i]; break;
            default: break;
        }
    }
    const int E = E_EDGES;
    const int* rows = edge_index;       // edge_index[0]
    const int* cols = edge_index + E;   // edge_index[1]

    float* out = (float*)d_out;
    int write_y = (out_size >= M_MASK * HID + M_MASK) ? 1 : 0;

    const int T = 256;
    // Launch order puts gemm(doc) at index 3 so ncu's fixed capture slot
    // (previously landing on launch #3) profiles the GEMM this time.
    // 0) init accumulators / deg / flags / counter
    init_kernel<<<(N_NODES * HID + T - 1) / T, T>>>();
    // 1) mask flags (must precede deg_compact)
    mask_set_kernel<<<(M_MASK + T - 1) / T, T>>>(mask_idx);
    // 2) fused weight W_eff = W_lin@W1, b_word = b_lin@W1
    weff_kernel<<<(301 * HID + T - 1) / T, T>>>(W_lin, W1, b_lin);
    // 3) xw1 doc part = doc@W1
    gemm64_kernel<<<(N_DOC + 127) / 128, 256>>>(doc, W1, nullptr,
                                                0, 0, 0, 0, 0, N_DOC, 768);
    // 4) xw1 word part = word@W_eff + b_word
    gemm64_kernel<<<(N_WORD + 127) / 128, 256>>>(word, nullptr, nullptr,
                                                 0, 1, 1, 0,
                                                 (long long)N_DOC * HID, N_WORD, 300);
    // 5) degree + masked-edge compaction
    deg_compact_kernel<<<(E + T - 1) / T, T>>>(cols, ew, E);
    // 6) normalization
    dis_kernel<<<(N_NODES + T - 1) / T, T>>>();
    // 7) layer-1 aggregation: half-warp per edge, vector REDs
    {
        int edges_per_block = T / 16;  // 16
        scatter1_kernel<<<(E + edges_per_block - 1) / edges_per_block, T>>>(
            rows, cols, ew, E);
    }
    // 8) layer 2 GEMM with fused relu epilogue of layer 1 (A built on the fly)
    gemm64_kernel<<<(N_NODES + 127) / 128, 256>>>(nullptr, W2, b1,
                                                  1, 0, 0, 1, 0, N_NODES, 64);
    // 9) layer-2 scatter over compacted masked-dst edges
    scatter2_kernel<<<1024, T>>>(rows, cols, ew);
    // 10) output gather
    final_kernel<<<(M_MASK * HID + T - 1) / T, T>>>(mask_idx, yv, b2, out, write_y);
}